// round 13
// baseline (speedup 1.0000x reference)
#include <cuda_runtime.h>
#include <cstdint>
#include <math.h>

#define BB 2
#define NN 2048
#define DM 1024
#define HH 16
#define DH 64
#define MM (BB*NN)      /* 4096 */
#define BH (BB*HH)      /* 32   */
#define EPSF 1e-6f

// ---------------- device scratch (no allocation allowed) -------------------
__device__ float g_Q [BH*NN*DH];     // [bh][n][d]  raw Q projection (normalized in attn)
__device__ float g_Kt[BH*DH*NN];     // [bh][d][n]  K transposed (normalized by norm_k_cols)
__device__ float g_V [BH*NN*DH];     // [bh][n][d]  (tf32-rounded)
__device__ float g_O [BH*NN*DH];     // [bh][n][d]  attention out (tf32-rounded)
__device__ float g_Wt[4*DM*DM];      // W^T for Wq,Wk,Wv,Wo (tf32-rounded, contiguous)
__device__ float g_Xr[MM*DM];        // X rounded to tf32

// ---------------- helpers ---------------------------------------------------
__device__ __forceinline__ float tf32r(float x) {
    float y; asm("cvt.rna.tf32.f32 %0, %1;" : "=f"(y) : "f"(x)); return y;
}
__device__ __forceinline__ void cp16(uint32_t dst, const void* src) {
    asm volatile("cp.async.cg.shared.global [%0], [%1], 16;" :: "r"(dst), "l"(src));
}
__device__ __forceinline__ void cp_commit() { asm volatile("cp.async.commit_group;"); }
template<int N> __device__ __forceinline__ void cp_wait() {
    asm volatile("cp.async.wait_group %0;" :: "n"(N));
}
__device__ __forceinline__ uint32_t smem_u32(const void* p) {
    uint32_t a;
    asm("{ .reg .u64 t; cvta.to.shared.u64 t, %1; cvt.u32.u64 %0, t; }" : "=r"(a) : "l"(p));
    return a;
}
__device__ __forceinline__ void mma_tf32(float* c, const uint32_t* a, const uint32_t* b) {
    asm volatile(
        "mma.sync.aligned.m16n8k8.row.col.f32.tf32.tf32.f32 "
        "{%0,%1,%2,%3}, {%4,%5,%6,%7}, {%8,%9}, {%0,%1,%2,%3};"
        : "+f"(c[0]), "+f"(c[1]), "+f"(c[2]), "+f"(c[3])
        : "r"(a[0]), "r"(a[1]), "r"(a[2]), "r"(a[3]), "r"(b[0]), "r"(b[1]));
}

// ---------------------------------------------------------------------------
// Pre-passes: round X to tf32; transpose + round all 4 weights (one launch)
// ---------------------------------------------------------------------------
__global__ __launch_bounds__(256) void round_x(const float* __restrict__ X)
{
    int i = blockIdx.x * 256 + threadIdx.x;
    float4 v = ((const float4*)X)[i];
    v.x = tf32r(v.x); v.y = tf32r(v.y); v.z = tf32r(v.z); v.w = tf32r(v.w);
    ((float4*)g_Xr)[i] = v;
}

__global__ __launch_bounds__(256) void transpose_w4(
    const float* __restrict__ W0, const float* __restrict__ W1,
    const float* __restrict__ W2, const float* __restrict__ W3)
{
    __shared__ float ts[32][33];
    const int slot = blockIdx.z;
    const float* W = (slot == 0) ? W0 : (slot == 1) ? W1 : (slot == 2) ? W2 : W3;
    float* Wt = g_Wt + (size_t)slot * DM * DM;
    int bx = blockIdx.x * 32, by = blockIdx.y * 32;
    #pragma unroll
    for (int i = 0; i < 32; i += 8)
        ts[threadIdx.y + i][threadIdx.x] = W[(size_t)(by + threadIdx.y + i) * DM + bx + threadIdx.x];
    __syncthreads();
    #pragma unroll
    for (int i = 0; i < 32; i += 8)
        Wt[(size_t)(bx + threadIdx.y + i) * DM + by + threadIdx.x] = tf32r(ts[threadIdx.x][threadIdx.y + i]);
}

// ---------------------------------------------------------------------------
// mma.sync tf32 GEMM. BM=128 BN=128 BK=32, 256 threads, warp tile 64x32.
// mode -1: fused QKV projection, C[4096 x 3072]; proj = blockIdx.x>>3
// mode  3: out = g_O @ Wo^T + bo (A gathered from g_O heads layout)
// ---------------------------------------------------------------------------
#define BK 32
#define LDS_ROW 36
#define TILE_F (128*LDS_ROW)
#define GEMM_SMEM (4*TILE_F*4)
#define KTILES (DM/BK)

__global__ __launch_bounds__(256, 2) void gemm_tc(
    const float* __restrict__ A, const float* __restrict__ Bt,
    const float* __restrict__ bias, float* __restrict__ out, int mode)
{
    extern __shared__ float sm[];
    float* sA[2] = { sm,            sm + 2*TILE_F };
    float* sB[2] = { sm + TILE_F,   sm + 3*TILE_F };

    const int tid  = threadIdx.x;
    const int wid  = tid >> 5;
    const int lane = tid & 31;
    const int lr   = lane >> 2;
    const int lc   = lane & 3;
    const int wm   = (wid & 1) * 64;
    const int wn   = (wid >> 1) * 32;
    const int m0   = blockIdx.y * 128;

    const int bx    = blockIdx.x;
    const int emode = (mode < 0) ? (bx >> 3) : mode;
    const int c0g   = bx * 128;
    const int c0    = (mode < 0) ? ((bx & 7) * 128) : c0g;

    const int lrow = tid >> 1, lhalf = tid & 1;
    const int am = m0 + lrow;
    const int ab = am >> 11, an = am & (NN - 1);
    const float* brow_base = Bt + (size_t)(c0g + lrow) * DM;
    const uint32_t sa_u[2] = { smem_u32(sA[0]), smem_u32(sA[1]) };
    const uint32_t sb_u[2] = { smem_u32(sB[0]), smem_u32(sB[1]) };
    const uint32_t dst_off = (uint32_t)lrow * (LDS_ROW*4) + (uint32_t)lhalf * 64;

    auto load_tile = [&](int t, int buf) {
        const int k0 = t * BK + lhalf * 16;
        const float* arow;
        if (mode == 3) {
            arow = g_O + ((size_t)(ab * HH + (k0 >> 6)) * NN + an) * DH + (k0 & 63);
        } else {
            arow = A + (size_t)am * DM + k0;
        }
        const float* brow = brow_base + k0;
        #pragma unroll
        for (int f = 0; f < 4; f++) {
            cp16(sa_u[buf] + dst_off + f * 16, arow + f * 4);
            cp16(sb_u[buf] + dst_off + f * 16, brow + f * 4);
        }
    };

    float acc[4][4][4] = {};

    load_tile(0, 0);
    cp_commit();

    for (int t = 0; t < KTILES; t++) {
        const int p = t & 1;
        if (t + 1 < KTILES) {
            load_tile(t + 1, 1 - p);
            cp_commit();
            cp_wait<1>();
        } else {
            cp_wait<0>();
        }
        __syncthreads();

        const float* Ab = sA[p];
        const float* Bb = sB[p];
        #pragma unroll
        for (int kk = 0; kk < 4; kk++) {
            const int k0 = kk * 8;
            uint32_t af[4][4], bf[4][2];
            #pragma unroll
            for (int mt = 0; mt < 4; mt++) {
                const int rb = wm + mt * 16;
                af[mt][0] = __float_as_uint(Ab[(rb +     lr) * LDS_ROW + k0 +     lc]);
                af[mt][1] = __float_as_uint(Ab[(rb + 8 + lr) * LDS_ROW + k0 +     lc]);
                af[mt][2] = __float_as_uint(Ab[(rb +     lr) * LDS_ROW + k0 + 4 + lc]);
                af[mt][3] = __float_as_uint(Ab[(rb + 8 + lr) * LDS_ROW + k0 + 4 + lc]);
            }
            #pragma unroll
            for (int nt = 0; nt < 4; nt++) {
                const int cb = wn + nt * 8;
                bf[nt][0] = __float_as_uint(Bb[(cb + lr) * LDS_ROW + k0 +     lc]);
                bf[nt][1] = __float_as_uint(Bb[(cb + lr) * LDS_ROW + k0 + 4 + lc]);
            }
            #pragma unroll
            for (int mt = 0; mt < 4; mt++)
                #pragma unroll
                for (int nt = 0; nt < 4; nt++)
                    mma_tf32(acc[mt][nt], af[mt], bf[nt]);
        }
        __syncthreads();
    }

    #pragma unroll
    for (int mt = 0; mt < 4; mt++) {
        #pragma unroll
        for (int half = 0; half < 2; half++) {
            const int m = m0 + wm + mt * 16 + half * 8 + lr;
            const int b = m >> 11, n = m & (NN - 1);
            #pragma unroll
            for (int nt = 0; nt < 4; nt++) {
                const int c = c0 + wn + nt * 8 + 2 * lc;
                const float v0 = acc[mt][nt][half * 2 + 0];
                const float v1 = acc[mt][nt][half * 2 + 1];
                if (emode == 3) {
                    float2 bv = *(const float2*)&bias[c];
                    *(float2*)&out[(size_t)m * DM + c] = make_float2(v0 + bv.x, v1 + bv.y);
                } else if (emode == 1) {
                    const int h = c >> 6, d = c & 63;
                    float* dst = g_Kt + ((size_t)(b * HH + h)) * DH * NN + n;
                    dst[(size_t)d * NN]       = v0;
                    dst[(size_t)(d + 1) * NN] = v1;
                } else if (emode == 2) {
                    const int h = c >> 6, d = c & 63;
                    *(float2*)&g_V[(((size_t)(b * HH + h)) * NN + n) * DH + d] =
                        make_float2(tf32r(v0), tf32r(v1));
                } else {
                    const int h = c >> 6, d = c & 63;
                    *(float2*)&g_Q[(((size_t)(b * HH + h)) * NN + n) * DH + d] = make_float2(v0, v1);
                }
            }
        }
    }
}

// ---------------------------------------------------------------------------
// L2-normalize K columns, two-pass (low regs; second read hits L2)
// ---------------------------------------------------------------------------
__global__ __launch_bounds__(256) void norm_k_cols()
{
    int gc = blockIdx.x * 256 + threadIdx.x;
    int bh = gc >> 11, n = gc & (NN-1);
    float* p = g_Kt + (size_t)bh * DH * NN + n;
    float ss = 0.f;
    #pragma unroll 8
    for (int d = 0; d < DH; d++) { float v = p[(size_t)d*NN]; ss += v*v; }
    float sc = 1.0f / (sqrtf(ss) + EPSF);
    #pragma unroll 8
    for (int d = 0; d < DH; d++) p[(size_t)d*NN] = tf32r(p[(size_t)d*NN]*sc);
}

// ---------------------------------------------------------------------------
// Tensor-core flash attention, 2 CTAs/SM, NO-MAX softmax.
// Q,K are L2-normalized -> scores in [-1/8, 1/8] -> exp(s) in [0.88,1.13]:
// softmax shift-invariance means we can drop the online max entirely.
// l accumulates per-thread across tiles; single quad-reduce at epilogue.
// ---------------------------------------------------------------------------
#define KROW 72
#define QROW 68
#define KV_F (64*KROW)
#define AT_SMEM ((4*KV_F + 128*QROW)*4)      /* 108544 bytes */

__global__ __launch_bounds__(256, 2) void attn_tc()
{
    extern __shared__ float sm[];
    float* Ks[2] = { sm,          sm + 2*KV_F };
    float* Vs[2] = { sm + KV_F,   sm + 3*KV_F };
    float* Qs    = sm + 4*KV_F;

    const int tid  = threadIdx.x;
    const int wid  = tid >> 5;
    const int lane = tid & 31;
    const int lr   = lane >> 2;              // 0..7
    const int lc   = lane & 3;               // 0..3
    const int qt   = gridDim.x - 1 - blockIdx.x;   // heavy blocks first
    const int bh   = blockIdx.y;
    const int qbase = qt * 128;
    const int T    = 2 * qt + 2;             // 64-key tiles

    const float* Qp = g_Q  + (size_t)bh * NN * DH;
    const float* Kp = g_Kt + (size_t)bh * DH * NN;
    const float* Vp = g_V  + (size_t)bh * NN * DH;

    const uint32_t ks_u[2] = { smem_u32(Ks[0]), smem_u32(Ks[1]) };
    const uint32_t vs_u[2] = { smem_u32(Vs[0]), smem_u32(Vs[1]) };
    const int ldrow = tid >> 2, ldseg = tid & 3;

    auto load_kv = [&](int t, int buf) {
        const int kbase = t * 64;
        const float* ksrc = Kp + (size_t)ldrow * NN + kbase + ldseg * 16;
        const float* vsrc = Vp + (size_t)(kbase + ldrow) * DH + ldseg * 16;
        const uint32_t doff = (uint32_t)ldrow * (KROW*4) + (uint32_t)ldseg * 64;
        #pragma unroll
        for (int f = 0; f < 4; f++) {
            cp16(ks_u[buf] + doff + f * 16, ksrc + f * 4);
            cp16(vs_u[buf] + doff + f * 16, vsrc + f * 4);
        }
    };

    load_kv(0, 0);
    cp_commit();

    // ---- stage Q: L2-normalize + scale 1/8 + tf32 round ----
    {
        const int row = tid >> 1, halfq = tid & 1;
        const float4* src = (const float4*)(Qp + (size_t)(qbase + row) * DH + halfq * 32);
        float4 v[8];
        float ss = 0.f;
        #pragma unroll
        for (int f = 0; f < 8; f++) {
            v[f] = src[f];
            ss += v[f].x*v[f].x + v[f].y*v[f].y + v[f].z*v[f].z + v[f].w*v[f].w;
        }
        ss += __shfl_xor_sync(0xffffffffu, ss, 1);
        const float sc = 0.125f / (sqrtf(ss) + EPSF);
        float4* dst = (float4*)(Qs + row * QROW + halfq * 32);
        #pragma unroll
        for (int f = 0; f < 8; f++)
            dst[f] = make_float4(tf32r(v[f].x * sc), tf32r(v[f].y * sc),
                                 tf32r(v[f].z * sc), tf32r(v[f].w * sc));
    }

    float l0 = 0.f, l1 = 0.f;                // per-thread partial row sums
    float o[8][4] = {};
    const int q0row = qbase + 16 * wid + lr;
    const int q1row = q0row + 8;
    const float* q0 = Qs + (16 * wid +     lr) * QROW;
    const float* q1 = Qs + (16 * wid + 8 + lr) * QROW;

    for (int t = 0; t < T; t++) {
        const int p = t & 1;
        __syncthreads();                       // buf 1-p reads done
        if (t + 1 < T) {
            load_kv(t + 1, 1 - p);
            cp_commit();
            cp_wait<1>();
        } else {
            cp_wait<0>();
        }
        __syncthreads();                       // tile t resident; Qs visible (t=0)

        // ---- S = Q K^T (scaled) ----
        float s[8][4] = {};
        const float* Kb = Ks[p];
        #pragma unroll
        for (int k8 = 0; k8 < 8; k8++) {
            uint32_t af[4];
            af[0] = __float_as_uint(q0[8*k8 +     lc]);
            af[1] = __float_as_uint(q1[8*k8 +     lc]);
            af[2] = __float_as_uint(q0[8*k8 + 4 + lc]);
            af[3] = __float_as_uint(q1[8*k8 + 4 + lc]);
            const float* kr0 = Kb + (8*k8 +     lc) * KROW;
            const float* kr1 = Kb + (8*k8 + 4 + lc) * KROW;
            #pragma unroll
            for (int hh = 0; hh < 2; hh++) {
                uint32_t bk[4][2];
                #pragma unroll
                for (int q = 0; q < 4; q++) {
                    const int nt = 4*hh + q;
                    bk[q][0] = __float_as_uint(kr0[8*nt + lr]);
                    bk[q][1] = __float_as_uint(kr1[8*nt + lr]);
                }
                #pragma unroll
                for (int q = 0; q < 4; q++)
                    mma_tf32(s[4*hh + q], af, bk[q]);
            }
        }

        // ---- no-max softmax: p = exp(s) (masked -> 0), accumulate local sums ----
        const int kbase = t * 64;
        const bool diag = (t >= T - 2);
        #pragma unroll
        for (int nt = 0; nt < 8; nt++) {
            #pragma unroll
            for (int c = 0; c < 2; c++) {
                float p0 = tf32r(__expf(s[nt][c]));
                float p1 = tf32r(__expf(s[nt][2 + c]));
                if (diag) {
                    const int j = kbase + 8*nt + 2*lc + c;
                    if (j > q0row) p0 = 0.f;
                    if (j > q1row) p1 = 0.f;
                }
                s[nt][c] = p0;  s[nt][2 + c] = p1;
                l0 += p0;  l1 += p1;
            }
        }

        // ---- O += P V  (C-frag -> A-frag via quad shuffles) ----
        const float* Vb = Vs[p];
        const int qlane = lane & ~3;
        const int src1 = qlane | (lc >> 1);
        const int src2 = qlane | (2 + (lc >> 1));
        const bool odd = (lc & 1);
        #pragma unroll
        for (int jt = 0; jt < 8; jt++) {
            uint32_t ap[4];
            {
                float a0 = __shfl_sync(0xffffffffu, s[jt][0], src1);
                float b0 = __shfl_sync(0xffffffffu, s[jt][1], src1);
                float a1 = __shfl_sync(0xffffffffu, s[jt][2], src1);
                float b1 = __shfl_sync(0xffffffffu, s[jt][3], src1);
                float a2 = __shfl_sync(0xffffffffu, s[jt][0], src2);
                float b2 = __shfl_sync(0xffffffffu, s[jt][1], src2);
                float a3 = __shfl_sync(0xffffffffu, s[jt][2], src2);
                float b3 = __shfl_sync(0xffffffffu, s[jt][3], src2);
                ap[0] = __float_as_uint(odd ? b0 : a0);
                ap[1] = __float_as_uint(odd ? b1 : a1);
                ap[2] = __float_as_uint(odd ? b2 : a2);
                ap[3] = __float_as_uint(odd ? b3 : a3);
            }
            const float* vr0 = Vb + (8*jt +     lc) * KROW;
            const float* vr1 = Vb + (8*jt + 4 + lc) * KROW;
            #pragma unroll
            for (int hh = 0; hh < 2; hh++) {
                uint32_t bv[4][2];
                #pragma unroll
                for (int q = 0; q < 4; q++) {
                    const int nt = 4*hh + q;
                    bv[q][0] = __float_as_uint(vr0[8*nt + lr]);
                    bv[q][1] = __float_as_uint(vr1[8*nt + lr]);
                }
                #pragma unroll
                for (int q = 0; q < 4; q++)
                    mma_tf32(o[4*hh + q], ap, bv[q]);
            }
        }
    }

    // ---- epilogue: reduce l across quad, O /= l, write heads layout ----
    l0 += __shfl_xor_sync(0xffffffffu, l0, 1);
    l0 += __shfl_xor_sync(0xffffffffu, l0, 2);
    l1 += __shfl_xor_sync(0xffffffffu, l1, 1);
    l1 += __shfl_xor_sync(0xffffffffu, l1, 2);
    const float inv0 = 1.0f / l0, inv1 = 1.0f / l1;
    float* Op = g_O + (size_t)bh * NN * DH;
    float* o0 = Op + (size_t)q0row * DH + 2 * lc;
    float* o1 = Op + (size_t)q1row * DH + 2 * lc;
    #pragma unroll
    for (int nt = 0; nt < 8; nt++) {
        *(float2*)(o0 + 8*nt) = make_float2(tf32r(o[nt][0] * inv0), tf32r(o[nt][1] * inv0));
        *(float2*)(o1 + 8*nt) = make_float2(tf32r(o[nt][2] * inv1), tf32r(o[nt][3] * inv1));
    }
}

// ---------------------------------------------------------------------------
extern "C" void kernel_launch(void* const* d_in, const int* in_sizes, int n_in,
                              void* d_out, int out_size)
{
    const float* X  = (const float*)d_in[0];
    const float* Wq = (const float*)d_in[1];
    const float* Wk = (const float*)d_in[2];
    const float* Wv = (const float*)d_in[3];
    const float* Wo = (const float*)d_in[4];
    const float* bo = (const float*)d_in[5];
    float* out = (float*)d_out;

    cudaFuncSetAttribute(gemm_tc, cudaFuncAttributeMaxDynamicSharedMemorySize, GEMM_SMEM);
    cudaFuncSetAttribute(attn_tc, cudaFuncAttributeMaxDynamicSharedMemorySize, AT_SMEM);

    round_x<<<(MM*DM)/(4*256), 256>>>(X);
    transpose_w4<<<dim3(32, 32, 4), dim3(32, 8)>>>(Wq, Wk, Wv, Wo);

    // __device__ symbols must be resolved to device addresses host-side.
    float* wt = nullptr;
    cudaGetSymbolAddress((void**)&wt, g_Wt);
    float* xr = nullptr;
    cudaGetSymbolAddress((void**)&xr, g_Xr);

    // fused QKV projection: C[4096 x 3072], 768 CTAs
    gemm_tc<<<dim3(3*DM/128, MM/128), 256, GEMM_SMEM>>>(xr, wt, nullptr, nullptr, -1);

    norm_k_cols<<<(BH*NN)/256, 256>>>();

    attn_tc<<<dim3(NN/128, BH), 256, AT_SMEM>>>();

    gemm_tc<<<dim3(DM/128, MM/128), 256, GEMM_SMEM>>>(nullptr, wt + 3*(size_t)DM*DM, bo, out, 3);
}

// round 14
// speedup vs baseline: 1.5445x; 1.5445x over previous
#include <cuda_runtime.h>
#include <cstdint>
#include <math.h>

#define BB 2
#define NN 2048
#define DM 1024
#define HH 16
#define DH 64
#define MM (BB*NN)      /* 4096 */
#define BH (BB*HH)      /* 32   */
#define EPSF 1e-6f

// ---------------- device scratch (no allocation allowed) -------------------
__device__ float g_Q [BH*NN*DH];     // [bh][n][d]  raw Q projection (normalized in attn)
__device__ float g_Kt[BH*DH*NN];     // [bh][d][n]  K transposed (normalized by norm_k_cols)
__device__ float g_V [BH*NN*DH];     // [bh][n][d]  (tf32-rounded)
__device__ float g_O [BH*NN*DH];     // [bh][n][d]  attention out (tf32-rounded)
__device__ float g_Wt[4*DM*DM];      // W^T for Wq,Wk,Wv,Wo (tf32-rounded, contiguous)
__device__ float g_Xr[MM*DM];        // X rounded to tf32

// ---------------- helpers ---------------------------------------------------
__device__ __forceinline__ float tf32r(float x) {
    float y; asm("cvt.rna.tf32.f32 %0, %1;" : "=f"(y) : "f"(x)); return y;
}
__device__ __forceinline__ void cp16(uint32_t dst, const void* src) {
    asm volatile("cp.async.cg.shared.global [%0], [%1], 16;" :: "r"(dst), "l"(src));
}
__device__ __forceinline__ void cp_commit() { asm volatile("cp.async.commit_group;"); }
template<int N> __device__ __forceinline__ void cp_wait() {
    asm volatile("cp.async.wait_group %0;" :: "n"(N));
}
__device__ __forceinline__ uint32_t smem_u32(const void* p) {
    uint32_t a;
    asm("{ .reg .u64 t; cvta.to.shared.u64 t, %1; cvt.u32.u64 %0, t; }" : "=r"(a) : "l"(p));
    return a;
}
__device__ __forceinline__ void mma_tf32(float* c, const uint32_t* a, const uint32_t* b) {
    asm volatile(
        "mma.sync.aligned.m16n8k8.row.col.f32.tf32.tf32.f32 "
        "{%0,%1,%2,%3}, {%4,%5,%6,%7}, {%8,%9}, {%0,%1,%2,%3};"
        : "+f"(c[0]), "+f"(c[1]), "+f"(c[2]), "+f"(c[3])
        : "r"(a[0]), "r"(a[1]), "r"(a[2]), "r"(a[3]), "r"(b[0]), "r"(b[1]));
}

// ---------------------------------------------------------------------------
// Pre-passes: round X to tf32; transpose + round all 4 weights (one launch)
// ---------------------------------------------------------------------------
__global__ __launch_bounds__(256) void round_x(const float* __restrict__ X)
{
    int i = blockIdx.x * 256 + threadIdx.x;
    float4 v = ((const float4*)X)[i];
    v.x = tf32r(v.x); v.y = tf32r(v.y); v.z = tf32r(v.z); v.w = tf32r(v.w);
    ((float4*)g_Xr)[i] = v;
}

__global__ __launch_bounds__(256) void transpose_w4(
    const float* __restrict__ W0, const float* __restrict__ W1,
    const float* __restrict__ W2, const float* __restrict__ W3)
{
    __shared__ float ts[32][33];
    const int slot = blockIdx.z;
    const float* W = (slot == 0) ? W0 : (slot == 1) ? W1 : (slot == 2) ? W2 : W3;
    float* Wt = g_Wt + (size_t)slot * DM * DM;
    int bx = blockIdx.x * 32, by = blockIdx.y * 32;
    #pragma unroll
    for (int i = 0; i < 32; i += 8)
        ts[threadIdx.y + i][threadIdx.x] = W[(size_t)(by + threadIdx.y + i) * DM + bx + threadIdx.x];
    __syncthreads();
    #pragma unroll
    for (int i = 0; i < 32; i += 8)
        Wt[(size_t)(bx + threadIdx.y + i) * DM + by + threadIdx.x] = tf32r(ts[threadIdx.x][threadIdx.y + i]);
}

// ---------------------------------------------------------------------------
// mma.sync tf32 GEMM. BM=128 BN=128 BK=32, 256 threads, warp tile 64x32.
// mode -1: fused QKV projection, C[4096 x 3072]; proj = blockIdx.x>>3
// mode  3: out = g_O @ Wo^T + bo (A gathered from g_O heads layout)
// ---------------------------------------------------------------------------
#define BK 32
#define LDS_ROW 36
#define TILE_F (128*LDS_ROW)
#define GEMM_SMEM (4*TILE_F*4)
#define KTILES (DM/BK)

__global__ __launch_bounds__(256, 2) void gemm_tc(
    const float* __restrict__ A, const float* __restrict__ Bt,
    const float* __restrict__ bias, float* __restrict__ out, int mode)
{
    extern __shared__ float sm[];
    float* sA[2] = { sm,            sm + 2*TILE_F };
    float* sB[2] = { sm + TILE_F,   sm + 3*TILE_F };

    const int tid  = threadIdx.x;
    const int wid  = tid >> 5;
    const int lane = tid & 31;
    const int lr   = lane >> 2;
    const int lc   = lane & 3;
    const int wm   = (wid & 1) * 64;
    const int wn   = (wid >> 1) * 32;
    const int m0   = blockIdx.y * 128;

    const int bx    = blockIdx.x;
    const int emode = (mode < 0) ? (bx >> 3) : mode;
    const int c0g   = bx * 128;
    const int c0    = (mode < 0) ? ((bx & 7) * 128) : c0g;

    const int lrow = tid >> 1, lhalf = tid & 1;
    const int am = m0 + lrow;
    const int ab = am >> 11, an = am & (NN - 1);
    const float* brow_base = Bt + (size_t)(c0g + lrow) * DM;
    const uint32_t sa_u[2] = { smem_u32(sA[0]), smem_u32(sA[1]) };
    const uint32_t sb_u[2] = { smem_u32(sB[0]), smem_u32(sB[1]) };
    const uint32_t dst_off = (uint32_t)lrow * (LDS_ROW*4) + (uint32_t)lhalf * 64;

    auto load_tile = [&](int t, int buf) {
        const int k0 = t * BK + lhalf * 16;
        const float* arow;
        if (mode == 3) {
            arow = g_O + ((size_t)(ab * HH + (k0 >> 6)) * NN + an) * DH + (k0 & 63);
        } else {
            arow = A + (size_t)am * DM + k0;
        }
        const float* brow = brow_base + k0;
        #pragma unroll
        for (int f = 0; f < 4; f++) {
            cp16(sa_u[buf] + dst_off + f * 16, arow + f * 4);
            cp16(sb_u[buf] + dst_off + f * 16, brow + f * 4);
        }
    };

    float acc[4][4][4] = {};

    load_tile(0, 0);
    cp_commit();

    for (int t = 0; t < KTILES; t++) {
        const int p = t & 1;
        if (t + 1 < KTILES) {
            load_tile(t + 1, 1 - p);
            cp_commit();
            cp_wait<1>();
        } else {
            cp_wait<0>();
        }
        __syncthreads();

        const float* Ab = sA[p];
        const float* Bb = sB[p];
        #pragma unroll
        for (int kk = 0; kk < 4; kk++) {
            const int k0 = kk * 8;
            uint32_t af[4][4], bf[4][2];
            #pragma unroll
            for (int mt = 0; mt < 4; mt++) {
                const int rb = wm + mt * 16;
                af[mt][0] = __float_as_uint(Ab[(rb +     lr) * LDS_ROW + k0 +     lc]);
                af[mt][1] = __float_as_uint(Ab[(rb + 8 + lr) * LDS_ROW + k0 +     lc]);
                af[mt][2] = __float_as_uint(Ab[(rb +     lr) * LDS_ROW + k0 + 4 + lc]);
                af[mt][3] = __float_as_uint(Ab[(rb + 8 + lr) * LDS_ROW + k0 + 4 + lc]);
            }
            #pragma unroll
            for (int nt = 0; nt < 4; nt++) {
                const int cb = wn + nt * 8;
                bf[nt][0] = __float_as_uint(Bb[(cb + lr) * LDS_ROW + k0 +     lc]);
                bf[nt][1] = __float_as_uint(Bb[(cb + lr) * LDS_ROW + k0 + 4 + lc]);
            }
            #pragma unroll
            for (int mt = 0; mt < 4; mt++)
                #pragma unroll
                for (int nt = 0; nt < 4; nt++)
                    mma_tf32(acc[mt][nt], af[mt], bf[nt]);
        }
        __syncthreads();
    }

    #pragma unroll
    for (int mt = 0; mt < 4; mt++) {
        #pragma unroll
        for (int half = 0; half < 2; half++) {
            const int m = m0 + wm + mt * 16 + half * 8 + lr;
            const int b = m >> 11, n = m & (NN - 1);
            #pragma unroll
            for (int nt = 0; nt < 4; nt++) {
                const int c = c0 + wn + nt * 8 + 2 * lc;
                const float v0 = acc[mt][nt][half * 2 + 0];
                const float v1 = acc[mt][nt][half * 2 + 1];
                if (emode == 3) {
                    float2 bv = *(const float2*)&bias[c];
                    *(float2*)&out[(size_t)m * DM + c] = make_float2(v0 + bv.x, v1 + bv.y);
                } else if (emode == 1) {
                    const int h = c >> 6, d = c & 63;
                    float* dst = g_Kt + ((size_t)(b * HH + h)) * DH * NN + n;
                    dst[(size_t)d * NN]       = v0;
                    dst[(size_t)(d + 1) * NN] = v1;
                } else if (emode == 2) {
                    const int h = c >> 6, d = c & 63;
                    *(float2*)&g_V[(((size_t)(b * HH + h)) * NN + n) * DH + d] =
                        make_float2(tf32r(v0), tf32r(v1));
                } else {
                    const int h = c >> 6, d = c & 63;
                    *(float2*)&g_Q[(((size_t)(b * HH + h)) * NN + n) * DH + d] = make_float2(v0, v1);
                }
            }
        }
    }
}

// ---------------------------------------------------------------------------
// L2-normalize K columns (rounds to tf32) — R12 one-pass version
// ---------------------------------------------------------------------------
__global__ __launch_bounds__(256) void norm_k_cols()
{
    int gc = blockIdx.x * 256 + threadIdx.x;
    int bh = gc >> 11, n = gc & (NN-1);
    float* p = g_Kt + (size_t)bh * DH * NN + n;
    float v[DH];
    float ss = 0.f;
    #pragma unroll
    for (int d = 0; d < DH; d++) { v[d] = p[(size_t)d*NN]; ss += v[d]*v[d]; }
    float sc = 1.0f / (sqrtf(ss) + EPSF);
    #pragma unroll
    for (int d = 0; d < DH; d++) p[(size_t)d*NN] = tf32r(v[d]*sc);
}

// ---------------------------------------------------------------------------
// Tensor-core flash attention, 2 CTAs/SM — R12 online-max structure.
// Only delta vs R12: P is NOT tf32-rounded after exp (MMA truncation bias on
// P cancels in P·V / l since l carries the same bias).
// ---------------------------------------------------------------------------
#define KROW 72
#define QROW 68
#define KV_F (64*KROW)
#define AT_SMEM ((4*KV_F + 128*QROW)*4)      /* 108544 bytes */

__global__ __launch_bounds__(256, 2) void attn_tc()
{
    extern __shared__ float sm[];
    float* Ks[2] = { sm,          sm + 2*KV_F };
    float* Vs[2] = { sm + KV_F,   sm + 3*KV_F };
    float* Qs    = sm + 4*KV_F;

    const int tid  = threadIdx.x;
    const int wid  = tid >> 5;
    const int lane = tid & 31;
    const int lr   = lane >> 2;              // 0..7
    const int lc   = lane & 3;               // 0..3
    const int qt   = gridDim.x - 1 - blockIdx.x;   // heavy blocks first
    const int bh   = blockIdx.y;
    const int qbase = qt * 128;
    const int T    = 2 * qt + 2;             // 64-key tiles

    const float* Qp = g_Q  + (size_t)bh * NN * DH;
    const float* Kp = g_Kt + (size_t)bh * DH * NN;
    const float* Vp = g_V  + (size_t)bh * NN * DH;

    const uint32_t ks_u[2] = { smem_u32(Ks[0]), smem_u32(Ks[1]) };
    const uint32_t vs_u[2] = { smem_u32(Vs[0]), smem_u32(Vs[1]) };
    const int ldrow = tid >> 2, ldseg = tid & 3;

    auto load_kv = [&](int t, int buf) {
        const int kbase = t * 64;
        const float* ksrc = Kp + (size_t)ldrow * NN + kbase + ldseg * 16;
        const float* vsrc = Vp + (size_t)(kbase + ldrow) * DH + ldseg * 16;
        const uint32_t doff = (uint32_t)ldrow * (KROW*4) + (uint32_t)ldseg * 64;
        #pragma unroll
        for (int f = 0; f < 4; f++) {
            cp16(ks_u[buf] + doff + f * 16, ksrc + f * 4);
            cp16(vs_u[buf] + doff + f * 16, vsrc + f * 4);
        }
    };

    load_kv(0, 0);
    cp_commit();

    // ---- stage Q: L2-normalize + scale 1/8 + tf32 round ----
    {
        const int row = tid >> 1, halfq = tid & 1;
        const float4* src = (const float4*)(Qp + (size_t)(qbase + row) * DH + halfq * 32);
        float4 v[8];
        float ss = 0.f;
        #pragma unroll
        for (int f = 0; f < 8; f++) {
            v[f] = src[f];
            ss += v[f].x*v[f].x + v[f].y*v[f].y + v[f].z*v[f].z + v[f].w*v[f].w;
        }
        ss += __shfl_xor_sync(0xffffffffu, ss, 1);   // pair tid^1 holds other half of row
        const float sc = 0.125f / (sqrtf(ss) + EPSF);
        float4* dst = (float4*)(Qs + row * QROW + halfq * 32);
        #pragma unroll
        for (int f = 0; f < 8; f++)
            dst[f] = make_float4(tf32r(v[f].x * sc), tf32r(v[f].y * sc),
                                 tf32r(v[f].z * sc), tf32r(v[f].w * sc));
    }

    float m0r = -INFINITY, m1r = -INFINITY, l0 = 0.f, l1 = 0.f;
    float o[8][4] = {};
    const int q0row = qbase + 16 * wid + lr;
    const int q1row = q0row + 8;
    const float* q0 = Qs + (16 * wid +     lr) * QROW;
    const float* q1 = Qs + (16 * wid + 8 + lr) * QROW;

    for (int t = 0; t < T; t++) {
        const int p = t & 1;
        __syncthreads();                       // buf 1-p reads done
        if (t + 1 < T) {
            load_kv(t + 1, 1 - p);
            cp_commit();
            cp_wait<1>();
        } else {
            cp_wait<0>();
        }
        __syncthreads();                       // tile t resident; Qs visible (t=0)

        // ---- S = Q K^T (scaled) ----
        float s[8][4] = {};
        const float* Kb = Ks[p];
        #pragma unroll
        for (int k8 = 0; k8 < 8; k8++) {
            uint32_t af[4];
            af[0] = __float_as_uint(q0[8*k8 +     lc]);
            af[1] = __float_as_uint(q1[8*k8 +     lc]);
            af[2] = __float_as_uint(q0[8*k8 + 4 + lc]);
            af[3] = __float_as_uint(q1[8*k8 + 4 + lc]);
            const float* kr0 = Kb + (8*k8 +     lc) * KROW;
            const float* kr1 = Kb + (8*k8 + 4 + lc) * KROW;
            #pragma unroll
            for (int hh = 0; hh < 2; hh++) {
                uint32_t bk[4][2];
                #pragma unroll
                for (int q = 0; q < 4; q++) {
                    const int nt = 4*hh + q;
                    bk[q][0] = __float_as_uint(kr0[8*nt + lr]);
                    bk[q][1] = __float_as_uint(kr1[8*nt + lr]);
                }
                #pragma unroll
                for (int q = 0; q < 4; q++)
                    mma_tf32(s[4*hh + q], af, bk[q]);
            }
        }

        // ---- online softmax on C-fragments (R12 structure) ----
        const int kbase = t * 64;
        const bool diag = (t >= T - 2);
        float mx0 = -INFINITY, mx1 = -INFINITY;
        #pragma unroll
        for (int nt = 0; nt < 8; nt++) {
            #pragma unroll
            for (int c = 0; c < 2; c++) {
                if (diag) {
                    const int j = kbase + 8*nt + 2*lc + c;
                    if (j > q0row) s[nt][c]     = -INFINITY;
                    if (j > q1row) s[nt][2 + c] = -INFINITY;
                }
                mx0 = fmaxf(mx0, s[nt][c]);
                mx1 = fmaxf(mx1, s[nt][2 + c]);
            }
        }
        mx0 = fmaxf(mx0, __shfl_xor_sync(0xffffffffu, mx0, 1));
        mx0 = fmaxf(mx0, __shfl_xor_sync(0xffffffffu, mx0, 2));
        mx1 = fmaxf(mx1, __shfl_xor_sync(0xffffffffu, mx1, 1));
        mx1 = fmaxf(mx1, __shfl_xor_sync(0xffffffffu, mx1, 2));
        const float mn0 = fmaxf(m0r, mx0), mn1 = fmaxf(m1r, mx1);
        const float cr0 = __expf(m0r - mn0), cr1 = __expf(m1r - mn1);
        float sum0 = 0.f, sum1 = 0.f;
        #pragma unroll
        for (int nt = 0; nt < 8; nt++) {
            #pragma unroll
            for (int c = 0; c < 2; c++) {
                float p0 = __expf(s[nt][c]     - mn0);
                float p1 = __expf(s[nt][2 + c] - mn1);
                s[nt][c] = p0;  s[nt][2 + c] = p1;
                sum0 += p0; sum1 += p1;
            }
        }
        sum0 += __shfl_xor_sync(0xffffffffu, sum0, 1);
        sum0 += __shfl_xor_sync(0xffffffffu, sum0, 2);
        sum1 += __shfl_xor_sync(0xffffffffu, sum1, 1);
        sum1 += __shfl_xor_sync(0xffffffffu, sum1, 2);
        l0 = l0 * cr0 + sum0;  m0r = mn0;
        l1 = l1 * cr1 + sum1;  m1r = mn1;
        #pragma unroll
        for (int nt = 0; nt < 8; nt++) {
            o[nt][0] *= cr0; o[nt][1] *= cr0;
            o[nt][2] *= cr1; o[nt][3] *= cr1;
        }

        // ---- O += P V  (C-frag -> A-frag via quad shuffles) ----
        const float* Vb = Vs[p];
        const int qlane = lane & ~3;
        const int src1 = qlane | (lc >> 1);
        const int src2 = qlane | (2 + (lc >> 1));
        const bool odd = (lc & 1);
        #pragma unroll
        for (int jt = 0; jt < 8; jt++) {
            uint32_t ap[4];
            {
                float a0 = __shfl_sync(0xffffffffu, s[jt][0], src1);
                float b0 = __shfl_sync(0xffffffffu, s[jt][1], src1);
                float a1 = __shfl_sync(0xffffffffu, s[jt][2], src1);
                float b1 = __shfl_sync(0xffffffffu, s[jt][3], src1);
                float a2 = __shfl_sync(0xffffffffu, s[jt][0], src2);
                float b2 = __shfl_sync(0xffffffffu, s[jt][1], src2);
                float a3 = __shfl_sync(0xffffffffu, s[jt][2], src2);
                float b3 = __shfl_sync(0xffffffffu, s[jt][3], src2);
                ap[0] = __float_as_uint(odd ? b0 : a0);
                ap[1] = __float_as_uint(odd ? b1 : a1);
                ap[2] = __float_as_uint(odd ? b2 : a2);
                ap[3] = __float_as_uint(odd ? b3 : a3);
            }
            const float* vr0 = Vb + (8*jt +     lc) * KROW;
            const float* vr1 = Vb + (8*jt + 4 + lc) * KROW;
            #pragma unroll
            for (int hh = 0; hh < 2; hh++) {
                uint32_t bv[4][2];
                #pragma unroll
                for (int q = 0; q < 4; q++) {
                    const int nt = 4*hh + q;
                    bv[q][0] = __float_as_uint(vr0[8*nt + lr]);
                    bv[q][1] = __float_as_uint(vr1[8*nt + lr]);
                }
                #pragma unroll
                for (int q = 0; q < 4; q++)
                    mma_tf32(o[4*hh + q], ap, bv[q]);
            }
        }
    }

    // ---- epilogue ----
    const float inv0 = 1.0f / l0, inv1 = 1.0f / l1;
    float* Op = g_O + (size_t)bh * NN * DH;
    float* o0 = Op + (size_t)q0row * DH + 2 * lc;
    float* o1 = Op + (size_t)q1row * DH + 2 * lc;
    #pragma unroll
    for (int nt = 0; nt < 8; nt++) {
        *(float2*)(o0 + 8*nt) = make_float2(tf32r(o[nt][0] * inv0), tf32r(o[nt][1] * inv0));
        *(float2*)(o1 + 8*nt) = make_float2(tf32r(o[nt][2] * inv1), tf32r(o[nt][3] * inv1));
    }
}

// ---------------------------------------------------------------------------
extern "C" void kernel_launch(void* const* d_in, const int* in_sizes, int n_in,
                              void* d_out, int out_size)
{
    const float* X  = (const float*)d_in[0];
    const float* Wq = (const float*)d_in[1];
    const float* Wk = (const float*)d_in[2];
    const float* Wv = (const float*)d_in[3];
    const float* Wo = (const float*)d_in[4];
    const float* bo = (const float*)d_in[5];
    float* out = (float*)d_out;

    cudaFuncSetAttribute(gemm_tc, cudaFuncAttributeMaxDynamicSharedMemorySize, GEMM_SMEM);
    cudaFuncSetAttribute(attn_tc, cudaFuncAttributeMaxDynamicSharedMemorySize, AT_SMEM);

    round_x<<<(MM*DM)/(4*256), 256>>>(X);
    transpose_w4<<<dim3(32, 32, 4), dim3(32, 8)>>>(Wq, Wk, Wv, Wo);

    // __device__ symbols must be resolved to device addresses host-side.
    float* wt = nullptr;
    cudaGetSymbolAddress((void**)&wt, g_Wt);
    float* xr = nullptr;
    cudaGetSymbolAddress((void**)&xr, g_Xr);

    // fused QKV projection: C[4096 x 3072], 768 CTAs
    gemm_tc<<<dim3(3*DM/128, MM/128), 256, GEMM_SMEM>>>(xr, wt, nullptr, nullptr, -1);

    norm_k_cols<<<(BH*NN)/256, 256>>>();

    attn_tc<<<dim3(NN/128, BH), 256, AT_SMEM>>>();

    gemm_tc<<<dim3(DM/128, MM/128), 256, GEMM_SMEM>>>(nullptr, wt + 3*(size_t)DM*DM, bo, out, 3);
}

// round 16
// speedup vs baseline: 1.6767x; 1.0856x over previous
#include <cuda_runtime.h>
#include <cuda_fp16.h>
#include <cstdint>
#include <math.h>

#define BB 2
#define NN 2048
#define DM 1024
#define HH 16
#define DH 64
#define MM (BB*NN)      /* 4096 */
#define BH (BB*HH)      /* 32   */
#define EPSF 1e-6f

// ---------------- device scratch (no allocation allowed) -------------------
__device__ __half g_Qh[BH*NN*DH];    // [bh][n][d]  raw Q projection (fp16)
__device__ __half g_Kh[BH*NN*DH];    // [bh][n][d]  K (normalized in place)
__device__ __half g_Vt[BH*DH*NN];    // [bh][d][n]  V transposed (fp16)
__device__ __half g_Oh[BH*NN*DH];    // [bh][n][d]  attention out (fp16)
__device__ __half g_Wh[4*DM*DM];     // W^T for Wq,Wk,Wv,Wo (fp16, contiguous)
__device__ __half g_Xh[MM*DM];       // X rounded to fp16

// ---------------- helpers ---------------------------------------------------
__device__ __forceinline__ void cp16(uint32_t dst, const void* src) {
    asm volatile("cp.async.cg.shared.global [%0], [%1], 16;" :: "r"(dst), "l"(src));
}
__device__ __forceinline__ void cp_commit() { asm volatile("cp.async.commit_group;"); }
template<int N> __device__ __forceinline__ void cp_wait() {
    asm volatile("cp.async.wait_group %0;" :: "n"(N));
}
__device__ __forceinline__ uint32_t smem_u32(const void* p) {
    uint32_t a;
    asm("{ .reg .u64 t; cvta.to.shared.u64 t, %1; cvt.u32.u64 %0, t; }" : "=r"(a) : "l"(p));
    return a;
}
__device__ __forceinline__ void mma_f16(float* c, const uint32_t* a, const uint32_t* b) {
    asm volatile(
        "mma.sync.aligned.m16n8k16.row.col.f32.f16.f16.f32 "
        "{%0,%1,%2,%3}, {%4,%5,%6,%7}, {%8,%9}, {%0,%1,%2,%3};"
        : "+f"(c[0]), "+f"(c[1]), "+f"(c[2]), "+f"(c[3])
        : "r"(a[0]), "r"(a[1]), "r"(a[2]), "r"(a[3]), "r"(b[0]), "r"(b[1]));
}
__device__ __forceinline__ uint32_t pack_h2(float lo, float hi) {
    uint32_t r;
    asm("cvt.rn.f16x2.f32 %0, %1, %2;" : "=r"(r) : "f"(hi), "f"(lo));
    return r;
}
__device__ __forceinline__ uint32_t ldh2(const __half* p) {   // aligned half2 load
    return *(const uint32_t*)p;
}

// ---------------------------------------------------------------------------
// Pre-passes: round X to fp16; transpose + round all 4 weights (one launch)
// ---------------------------------------------------------------------------
__global__ __launch_bounds__(256) void round_x(const float* __restrict__ X)
{
    int i = blockIdx.x * 256 + threadIdx.x;
    float4 v = ((const float4*)X)[i];
    uint2 o;
    o.x = pack_h2(v.x, v.y);
    o.y = pack_h2(v.z, v.w);
    ((uint2*)g_Xh)[i] = o;
}

__global__ __launch_bounds__(256) void transpose_w4(
    const float* __restrict__ W0, const float* __restrict__ W1,
    const float* __restrict__ W2, const float* __restrict__ W3)
{
    __shared__ float ts[32][33];
    const int slot = blockIdx.z;
    const float* W = (slot == 0) ? W0 : (slot == 1) ? W1 : (slot == 2) ? W2 : W3;
    __half* Wt = g_Wh + (size_t)slot * DM * DM;
    int bx = blockIdx.x * 32, by = blockIdx.y * 32;
    #pragma unroll
    for (int i = 0; i < 32; i += 8)
        ts[threadIdx.y + i][threadIdx.x] = W[(size_t)(by + threadIdx.y + i) * DM + bx + threadIdx.x];
    __syncthreads();
    #pragma unroll
    for (int i = 0; i < 32; i += 8)
        Wt[(size_t)(bx + threadIdx.y + i) * DM + by + threadIdx.x] =
            __float2half_rn(ts[threadIdx.x][threadIdx.y + i]);
}

// ---------------------------------------------------------------------------
// fp16 mma.sync GEMM: C[4096 x {3072|1024}] = A @ Bt^T  (Bt [n][k] halves)
// BM=128 BN=128 BK=32, 256 threads, warp tile 64x32, m16n8k16.
// mode -1: fused QKV; proj = blockIdx.x>>3 (0->g_Qh, 1->g_Kh, 2->g_Vt transp.)
// mode  3: out = g_Oh @ Wo^T + bo (fp32 out)
// ---------------------------------------------------------------------------
#define BK 32
#define AP 40                          /* halves per smem row */
#define TILE_H (128*AP)                /* halves per tile buffer */
#define GEMM_SMEM (4*TILE_H*2)         /* bytes: 2 buf x (A+B) */
#define KTILES (DM/BK)

__global__ __launch_bounds__(256, 2) void gemm_h(
    const __half* __restrict__ A, const __half* __restrict__ Bt,
    const float* __restrict__ bias, float* __restrict__ out, int mode)
{
    extern __shared__ __half smh[];
    __half* sA[2] = { smh,            smh + 2*TILE_H };
    __half* sB[2] = { smh + TILE_H,   smh + 3*TILE_H };

    const int tid  = threadIdx.x;
    const int wid  = tid >> 5;
    const int lane = tid & 31;
    const int lr   = lane >> 2;
    const int lc   = lane & 3;
    const int wm   = (wid & 1) * 64;
    const int wn   = (wid >> 1) * 32;
    const int m0   = blockIdx.y * 128;

    const int bx    = blockIdx.x;
    const int emode = (mode < 0) ? (bx >> 3) : mode;
    const int c0g   = bx * 128;
    const int c0    = (mode < 0) ? ((bx & 7) * 128) : c0g;

    const int lrow = tid & 127, lseg = tid >> 7;      // row, 32B-segment
    const int am = m0 + lrow;
    const int ab = am >> 11, an = am & (NN - 1);
    const __half* brow_base = Bt + (size_t)(c0g + lrow) * DM;
    const uint32_t sa_u[2] = { smem_u32(sA[0]), smem_u32(sA[1]) };
    const uint32_t sb_u[2] = { smem_u32(sB[0]), smem_u32(sB[1]) };
    const uint32_t dst_off = (uint32_t)lrow * (AP*2) + (uint32_t)lseg * 32;

    auto load_tile = [&](int t, int buf) {
        const int k0 = t * BK + lseg * 16;            // halves
        const __half* arow;
        if (mode == 3) {
            arow = g_Oh + ((size_t)(ab * HH + (k0 >> 6)) * NN + an) * DH + (k0 & 63);
        } else {
            arow = A + (size_t)am * DM + k0;
        }
        const __half* brow = brow_base + k0;
        #pragma unroll
        for (int f = 0; f < 2; f++) {
            cp16(sa_u[buf] + dst_off + f * 16, arow + f * 8);
            cp16(sb_u[buf] + dst_off + f * 16, brow + f * 8);
        }
    };

    float acc[4][4][4] = {};

    load_tile(0, 0);
    cp_commit();

    for (int t = 0; t < KTILES; t++) {
        const int p = t & 1;
        if (t + 1 < KTILES) {
            load_tile(t + 1, 1 - p);
            cp_commit();
            cp_wait<1>();
        } else {
            cp_wait<0>();
        }
        __syncthreads();

        const __half* Ab = sA[p];
        const __half* Bb = sB[p];
        #pragma unroll
        for (int kg = 0; kg < 2; kg++) {              // two k16 groups in BK=32
            const int k0 = kg * 16 + 2 * lc;
            uint32_t af[4][4], bf[4][2];
            #pragma unroll
            for (int mt = 0; mt < 4; mt++) {
                const int rb = wm + mt * 16;
                af[mt][0] = ldh2(&Ab[(rb +     lr) * AP + k0    ]);
                af[mt][1] = ldh2(&Ab[(rb + 8 + lr) * AP + k0    ]);
                af[mt][2] = ldh2(&Ab[(rb +     lr) * AP + k0 + 8]);
                af[mt][3] = ldh2(&Ab[(rb + 8 + lr) * AP + k0 + 8]);
            }
            #pragma unroll
            for (int nt = 0; nt < 4; nt++) {
                const int cb = wn + nt * 8;
                bf[nt][0] = ldh2(&Bb[(cb + lr) * AP + k0    ]);
                bf[nt][1] = ldh2(&Bb[(cb + lr) * AP + k0 + 8]);
            }
            #pragma unroll
            for (int mt = 0; mt < 4; mt++)
                #pragma unroll
                for (int nt = 0; nt < 4; nt++)
                    mma_f16(acc[mt][nt], af[mt], bf[nt]);
        }
        __syncthreads();
    }

    #pragma unroll
    for (int mt = 0; mt < 4; mt++) {
        #pragma unroll
        for (int half = 0; half < 2; half++) {
            const int m = m0 + wm + mt * 16 + half * 8 + lr;
            const int b = m >> 11, n = m & (NN - 1);
            #pragma unroll
            for (int nt = 0; nt < 4; nt++) {
                const int c = c0 + wn + nt * 8 + 2 * lc;
                const float v0 = acc[mt][nt][half * 2 + 0];
                const float v1 = acc[mt][nt][half * 2 + 1];
                if (emode == 3) {
                    float2 bv = *(const float2*)&bias[c];
                    *(float2*)&out[(size_t)m * DM + c] = make_float2(v0 + bv.x, v1 + bv.y);
                } else if (emode == 2) {
                    // V transposed: [bh][d][n], scattered half stores
                    const int h = c >> 6, d = c & 63;
                    __half* dst = g_Vt + ((size_t)(b * HH + h)) * DH * NN + n;
                    dst[(size_t)d * NN]       = __float2half_rn(v0);
                    dst[(size_t)(d + 1) * NN] = __float2half_rn(v1);
                } else {
                    // Q (emode 0) / K raw (emode 1): heads layout, half2 store
                    const int h = c >> 6, d = c & 63;
                    __half* dst = (emode == 0) ? g_Qh : g_Kh;
                    uint32_t pk = pack_h2(v0, v1);
                    *(uint32_t*)&dst[(((size_t)(b * HH + h)) * NN + n) * DH + d] = pk;
                }
            }
        }
    }
}

// ---------------------------------------------------------------------------
// L2-normalize K rows ([bh][n][d] fp16, warp per row; lane holds half2)
// ---------------------------------------------------------------------------
__global__ __launch_bounds__(256) void norm_k_rows()
{
    const int w    = (blockIdx.x * 256 + threadIdx.x) >> 5;   // 0 .. BH*NN-1
    const int lane = threadIdx.x & 31;
    uint32_t* p = (uint32_t*)(g_Kh + (size_t)w * DH) + lane;
    uint32_t pk = *p;
    float2 v = __half22float2(*(__half2*)&pk);
    float ss = v.x*v.x + v.y*v.y;
    #pragma unroll
    for (int off = 16; off; off >>= 1) ss += __shfl_xor_sync(0xffffffffu, ss, off);
    const float sc = 1.0f / (sqrtf(ss) + EPSF);
    *p = pack_h2(v.x * sc, v.y * sc);
}

// ---------------------------------------------------------------------------
// fp16 tensor-core flash attention, 2 CTAs/SM, online-max softmax (R14 form).
// K smem [j][d], V smem [d][j] (from g_Vt), Q smem [q][d] (normalized+1/8).
// P C-frag == PV A-frag layout for fp16: conversion is f16x2 packs, 0 shfl.
// ---------------------------------------------------------------------------
#define KP 72
#define KV_H (64*KP)                       /* halves per K (or V) buffer */
#define AT_SMEM ((4*KV_H + 128*KP)*2)      /* 55296 bytes */

__global__ __launch_bounds__(256, 2) void attn_h()
{
    extern __shared__ __half smh[];
    __half* Ks[2] = { smh,          smh + 2*KV_H };
    __half* Vs[2] = { smh + KV_H,   smh + 3*KV_H };
    __half* Qs    = smh + 4*KV_H;

    const int tid  = threadIdx.x;
    const int wid  = tid >> 5;
    const int lane = tid & 31;
    const int lr   = lane >> 2;              // 0..7
    const int lc   = lane & 3;               // 0..3
    const int qt   = gridDim.x - 1 - blockIdx.x;   // heavy blocks first
    const int bh   = blockIdx.y;
    const int qbase = qt * 128;
    const int T    = 2 * qt + 2;             // 64-key tiles

    const __half* Qp = g_Qh + (size_t)bh * NN * DH;
    const __half* Kp = g_Kh + (size_t)bh * NN * DH;
    const __half* Vp = g_Vt + (size_t)bh * DH * NN;

    const uint32_t ks_u[2] = { smem_u32(Ks[0]), smem_u32(Ks[1]) };
    const uint32_t vs_u[2] = { smem_u32(Vs[0]), smem_u32(Vs[1]) };
    const int ldrow = tid & 63, ldseg = tid >> 6;     // row, 32B segment (0..3)

    auto load_kv = [&](int t, int buf) {
        const int kbase = t * 64;
        const __half* ksrc = Kp + (size_t)(kbase + ldrow) * DH + ldseg * 16;
        const __half* vsrc = Vp + (size_t)ldrow * NN + kbase + ldseg * 16;
        const uint32_t doff = (uint32_t)ldrow * (KP*2) + (uint32_t)ldseg * 32;
        #pragma unroll
        for (int f = 0; f < 2; f++) {
            cp16(ks_u[buf] + doff + f * 16, ksrc + f * 8);
            cp16(vs_u[buf] + doff + f * 16, vsrc + f * 8);
        }
    };

    load_kv(0, 0);
    cp_commit();

    // ---- stage Q: L2-normalize + scale 1/8, fp16 ----
    // FIX vs R15: each thread covers 32 halves (uint4 x 4 = 64B), not 16.
    {
        const int row = tid >> 1, halfq = tid & 1;
        const uint4* src = (const uint4*)(Qp + (size_t)(qbase + row) * DH + halfq * 32);
        uint4 raw[4];
        float2 v[16];
        float ss = 0.f;
        #pragma unroll
        for (int f = 0; f < 4; f++) {
            raw[f] = src[f];
            v[4*f+0] = __half22float2(*(__half2*)&raw[f].x);
            v[4*f+1] = __half22float2(*(__half2*)&raw[f].y);
            v[4*f+2] = __half22float2(*(__half2*)&raw[f].z);
            v[4*f+3] = __half22float2(*(__half2*)&raw[f].w);
        }
        #pragma unroll
        for (int f = 0; f < 16; f++) ss += v[f].x*v[f].x + v[f].y*v[f].y;
        ss += __shfl_xor_sync(0xffffffffu, ss, 1);   // pair covers other 32 halves
        const float sc = 0.125f / (sqrtf(ss) + EPSF);
        uint4* dst = (uint4*)(Qs + row * KP + halfq * 32);
        #pragma unroll
        for (int f = 0; f < 4; f++) {
            uint4 o;
            o.x = pack_h2(v[4*f+0].x * sc, v[4*f+0].y * sc);
            o.y = pack_h2(v[4*f+1].x * sc, v[4*f+1].y * sc);
            o.z = pack_h2(v[4*f+2].x * sc, v[4*f+2].y * sc);
            o.w = pack_h2(v[4*f+3].x * sc, v[4*f+3].y * sc);
            dst[f] = o;
        }
    }

    float m0r = -INFINITY, m1r = -INFINITY, l0 = 0.f, l1 = 0.f;
    float o[8][4] = {};
    const int q0row = qbase + 16 * wid + lr;
    const int q1row = q0row + 8;
    const __half* q0 = Qs + (16 * wid +     lr) * KP;
    const __half* q1 = Qs + (16 * wid + 8 + lr) * KP;

    for (int t = 0; t < T; t++) {
        const int p = t & 1;
        __syncthreads();                       // buf 1-p reads done
        if (t + 1 < T) {
            load_kv(t + 1, 1 - p);
            cp_commit();
            cp_wait<1>();
        } else {
            cp_wait<0>();
        }
        __syncthreads();                       // tile t resident; Qs visible (t=0)

        // ---- S = Q K^T (pre-scaled) ----
        float s[8][4] = {};
        const __half* Kb = Ks[p];
        #pragma unroll
        for (int kg = 0; kg < 4; kg++) {       // d in 16-chunks
            const int k0 = kg * 16 + 2 * lc;
            uint32_t af[4];
            af[0] = ldh2(&q0[k0    ]);
            af[1] = ldh2(&q1[k0    ]);
            af[2] = ldh2(&q0[k0 + 8]);
            af[3] = ldh2(&q1[k0 + 8]);
            #pragma unroll
            for (int nt = 0; nt < 8; nt++) {
                uint32_t bk[2];
                bk[0] = ldh2(&Kb[(8*nt + lr) * KP + k0    ]);
                bk[1] = ldh2(&Kb[(8*nt + lr) * KP + k0 + 8]);
                mma_f16(s[nt], af, bk);
            }
        }

        // ---- online softmax on C-fragments (R14 structure) ----
        const int kbase = t * 64;
        const bool diag = (t >= T - 2);
        float mx0 = -INFINITY, mx1 = -INFINITY;
        #pragma unroll
        for (int nt = 0; nt < 8; nt++) {
            #pragma unroll
            for (int c = 0; c < 2; c++) {
                if (diag) {
                    const int j = kbase + 8*nt + 2*lc + c;
                    if (j > q0row) s[nt][c]     = -INFINITY;
                    if (j > q1row) s[nt][2 + c] = -INFINITY;
                }
                mx0 = fmaxf(mx0, s[nt][c]);
                mx1 = fmaxf(mx1, s[nt][2 + c]);
            }
        }
        mx0 = fmaxf(mx0, __shfl_xor_sync(0xffffffffu, mx0, 1));
        mx0 = fmaxf(mx0, __shfl_xor_sync(0xffffffffu, mx0, 2));
        mx1 = fmaxf(mx1, __shfl_xor_sync(0xffffffffu, mx1, 1));
        mx1 = fmaxf(mx1, __shfl_xor_sync(0xffffffffu, mx1, 2));
        const float mn0 = fmaxf(m0r, mx0), mn1 = fmaxf(m1r, mx1);
        const float cr0 = __expf(m0r - mn0), cr1 = __expf(m1r - mn1);
        float sum0 = 0.f, sum1 = 0.f;
        #pragma unroll
        for (int nt = 0; nt < 8; nt++) {
            #pragma unroll
            for (int c = 0; c < 2; c++) {
                float p0 = __expf(s[nt][c]     - mn0);
                float p1 = __expf(s[nt][2 + c] - mn1);
                s[nt][c] = p0;  s[nt][2 + c] = p1;
                sum0 += p0; sum1 += p1;
            }
        }
        sum0 += __shfl_xor_sync(0xffffffffu, sum0, 1);
        sum0 += __shfl_xor_sync(0xffffffffu, sum0, 2);
        sum1 += __shfl_xor_sync(0xffffffffu, sum1, 1);
        sum1 += __shfl_xor_sync(0xffffffffu, sum1, 2);
        l0 = l0 * cr0 + sum0;  m0r = mn0;
        l1 = l1 * cr1 + sum1;  m1r = mn1;
        #pragma unroll
        for (int nt = 0; nt < 8; nt++) {
            o[nt][0] *= cr0; o[nt][1] *= cr0;
            o[nt][2] *= cr1; o[nt][3] *= cr1;
        }

        // ---- O += P V  (C-frag -> A-frag: direct f16x2 packs, no shuffles) ----
        const __half* Vb = Vs[p];
        #pragma unroll
        for (int kg = 0; kg < 4; kg++) {       // j in 16-chunks = jt pair (2kg, 2kg+1)
            uint32_t ap[4];
            ap[0] = pack_h2(s[2*kg  ][0], s[2*kg  ][1]);
            ap[1] = pack_h2(s[2*kg  ][2], s[2*kg  ][3]);
            ap[2] = pack_h2(s[2*kg+1][0], s[2*kg+1][1]);
            ap[3] = pack_h2(s[2*kg+1][2], s[2*kg+1][3]);
            const int k0 = kg * 16 + 2 * lc;
            #pragma unroll
            for (int nt = 0; nt < 8; nt++) {   // d in 8-chunks
                uint32_t bv[2];
                bv[0] = ldh2(&Vb[(8*nt + lr) * KP + k0    ]);
                bv[1] = ldh2(&Vb[(8*nt + lr) * KP + k0 + 8]);
                mma_f16(o[nt], ap, bv);
            }
        }
    }

    // ---- epilogue: O /= l, fp16, heads layout ----
    const float inv0 = 1.0f / l0, inv1 = 1.0f / l1;
    __half* Op = g_Oh + (size_t)bh * NN * DH;
    __half* o0 = Op + (size_t)q0row * DH + 2 * lc;
    __half* o1 = Op + (size_t)q1row * DH + 2 * lc;
    #pragma unroll
    for (int nt = 0; nt < 8; nt++) {
        *(uint32_t*)(o0 + 8*nt) = pack_h2(o[nt][0] * inv0, o[nt][1] * inv0);
        *(uint32_t*)(o1 + 8*nt) = pack_h2(o[nt][2] * inv1, o[nt][3] * inv1);
    }
}

// ---------------------------------------------------------------------------
extern "C" void kernel_launch(void* const* d_in, const int* in_sizes, int n_in,
                              void* d_out, int out_size)
{
    const float* X  = (const float*)d_in[0];
    const float* Wq = (const float*)d_in[1];
    const float* Wk = (const float*)d_in[2];
    const float* Wv = (const float*)d_in[3];
    const float* Wo = (const float*)d_in[4];
    const float* bo = (const float*)d_in[5];
    float* out = (float*)d_out;

    cudaFuncSetAttribute(gemm_h, cudaFuncAttributeMaxDynamicSharedMemorySize, GEMM_SMEM);
    cudaFuncSetAttribute(attn_h, cudaFuncAttributeMaxDynamicSharedMemorySize, AT_SMEM);

    round_x<<<(MM*DM)/(4*256), 256>>>(X);
    transpose_w4<<<dim3(32, 32, 4), dim3(32, 8)>>>(Wq, Wk, Wv, Wo);

    // __device__ symbols must be resolved to device addresses host-side.
    __half* wh = nullptr;
    cudaGetSymbolAddress((void**)&wh, g_Wh);
    __half* xh = nullptr;
    cudaGetSymbolAddress((void**)&xh, g_Xh);

    // fused QKV projection: C[4096 x 3072], 768 CTAs
    gemm_h<<<dim3(3*DM/128, MM/128), 256, GEMM_SMEM>>>(xh, wh, nullptr, nullptr, -1);

    norm_k_rows<<<(BH*NN)/8, 256>>>();

    attn_h<<<dim3(NN/128, BH), 256, AT_SMEM>>>();

    gemm_h<<<dim3(DM/128, MM/128), 256, GEMM_SMEM>>>(nullptr, wh + 3*(size_t)DM*DM, bo, out, 3);
}

// round 17
// speedup vs baseline: 2.9998x; 1.7891x over previous
#include <cuda_runtime.h>
#include <cuda_fp16.h>
#include <cstdint>
#include <math.h>

#define BB 2
#define NN 2048
#define DM 1024
#define HH 16
#define DH 64
#define MM (BB*NN)      /* 4096 */
#define BH (BB*HH)      /* 32   */
#define EPSF 1e-6f

// ---------------- device scratch (no allocation allowed) -------------------
__device__ __half g_Qh[BH*NN*DH];    // [bh][n][d]  raw Q projection (fp16)
__device__ __half g_Kh[BH*NN*DH];    // [bh][n][d]  K (normalized in place)
__device__ __half g_Vh[BH*NN*DH];    // [bh][n][d]  V heads layout (fp16)
__device__ __half g_Oh[BH*NN*DH];    // [bh][n][d]  attention out (fp16)
__device__ __half g_Wh[4*DM*DM];     // W^T for Wq,Wk,Wv,Wo (fp16, contiguous)
__device__ __half g_Xh[MM*DM];       // X rounded to fp16

// ---------------- helpers ---------------------------------------------------
__device__ __forceinline__ void cp16(uint32_t dst, const void* src) {
    asm volatile("cp.async.cg.shared.global [%0], [%1], 16;" :: "r"(dst), "l"(src));
}
__device__ __forceinline__ void cp_commit() { asm volatile("cp.async.commit_group;"); }
template<int N> __device__ __forceinline__ void cp_wait() {
    asm volatile("cp.async.wait_group %0;" :: "n"(N));
}
__device__ __forceinline__ uint32_t smem_u32(const void* p) {
    uint32_t a;
    asm("{ .reg .u64 t; cvta.to.shared.u64 t, %1; cvt.u32.u64 %0, t; }" : "=r"(a) : "l"(p));
    return a;
}
__device__ __forceinline__ void mma_f16(float* c, const uint32_t* a, const uint32_t* b) {
    asm volatile(
        "mma.sync.aligned.m16n8k16.row.col.f32.f16.f16.f32 "
        "{%0,%1,%2,%3}, {%4,%5,%6,%7}, {%8,%9}, {%0,%1,%2,%3};"
        : "+f"(c[0]), "+f"(c[1]), "+f"(c[2]), "+f"(c[3])
        : "r"(a[0]), "r"(a[1]), "r"(a[2]), "r"(a[3]), "r"(b[0]), "r"(b[1]));
}
__device__ __forceinline__ uint32_t pack_h2(float lo, float hi) {
    uint32_t r;
    asm("cvt.rn.f16x2.f32 %0, %1, %2;" : "=r"(r) : "f"(hi), "f"(lo));
    return r;
}
#define LDSM_X4(r0, r1, r2, r3, addr) \
    asm volatile("ldmatrix.sync.aligned.m8n8.x4.shared.b16 {%0,%1,%2,%3}, [%4];" \
        : "=r"(r0), "=r"(r1), "=r"(r2), "=r"(r3) : "r"(addr))
#define LDSM_X4_T(r0, r1, r2, r3, addr) \
    asm volatile("ldmatrix.sync.aligned.m8n8.x4.trans.shared.b16 {%0,%1,%2,%3}, [%4];" \
        : "=r"(r0), "=r"(r1), "=r"(r2), "=r"(r3) : "r"(addr))

// ---------------------------------------------------------------------------
// Pre-passes: round X to fp16; transpose + round all 4 weights (one launch)
// ---------------------------------------------------------------------------
__global__ __launch_bounds__(256) void round_x(const float* __restrict__ X)
{
    int i = blockIdx.x * 256 + threadIdx.x;
    float4 v = ((const float4*)X)[i];
    uint2 o;
    o.x = pack_h2(v.x, v.y);
    o.y = pack_h2(v.z, v.w);
    ((uint2*)g_Xh)[i] = o;
}

__global__ __launch_bounds__(256) void transpose_w4(
    const float* __restrict__ W0, const float* __restrict__ W1,
    const float* __restrict__ W2, const float* __restrict__ W3)
{
    __shared__ float ts[32][33];
    const int slot = blockIdx.z;
    const float* W = (slot == 0) ? W0 : (slot == 1) ? W1 : (slot == 2) ? W2 : W3;
    __half* Wt = g_Wh + (size_t)slot * DM * DM;
    int bx = blockIdx.x * 32, by = blockIdx.y * 32;
    #pragma unroll
    for (int i = 0; i < 32; i += 8)
        ts[threadIdx.y + i][threadIdx.x] = W[(size_t)(by + threadIdx.y + i) * DM + bx + threadIdx.x];
    __syncthreads();
    #pragma unroll
    for (int i = 0; i < 32; i += 8)
        Wt[(size_t)(bx + threadIdx.y + i) * DM + by + threadIdx.x] =
            __float2half_rn(ts[threadIdx.x][threadIdx.y + i]);
}

// ---------------------------------------------------------------------------
// fp16 mma.sync GEMM with ldmatrix fragment loads.
// BM=128 BN=128 BK=32, 256 threads, warp tile 64x32, m16n8k16.
// mode -1: fused QKV; proj = blockIdx.x>>3 (0->g_Qh, 1->g_Kh, 2->g_Vh)
// mode  3: out = g_Oh @ Wo^T + bo (fp32 out)
// ---------------------------------------------------------------------------
#define BK 32
#define AP 40                          /* halves per smem row */
#define TILE_H (128*AP)
#define GEMM_SMEM (4*TILE_H*2)
#define KTILES (DM/BK)

__global__ __launch_bounds__(256, 2) void gemm_h(
    const __half* __restrict__ A, const __half* __restrict__ Bt,
    const float* __restrict__ bias, float* __restrict__ out, int mode)
{
    extern __shared__ __half smh[];
    __half* sA[2] = { smh,            smh + 2*TILE_H };
    __half* sB[2] = { smh + TILE_H,   smh + 3*TILE_H };

    const int tid  = threadIdx.x;
    const int wid  = tid >> 5;
    const int lane = tid & 31;
    const int lr   = lane >> 2;
    const int lc   = lane & 3;
    const int wm   = (wid & 1) * 64;
    const int wn   = (wid >> 1) * 32;
    const int m0   = blockIdx.y * 128;

    const int bx    = blockIdx.x;
    const int emode = (mode < 0) ? (bx >> 3) : mode;
    const int c0g   = bx * 128;
    const int c0    = (mode < 0) ? ((bx & 7) * 128) : c0g;

    const int lrow = tid & 127, lseg = tid >> 7;      // cp.async row, 32B-segment
    const int am = m0 + lrow;
    const int ab = am >> 11, an = am & (NN - 1);
    const __half* brow_base = Bt + (size_t)(c0g + lrow) * DM;
    const uint32_t sa_u[2] = { smem_u32(sA[0]), smem_u32(sA[1]) };
    const uint32_t sb_u[2] = { smem_u32(sB[0]), smem_u32(sB[1]) };
    const uint32_t dst_off = (uint32_t)lrow * (AP*2) + (uint32_t)lseg * 32;

    // ldmatrix lane-address offsets (bytes)
    const int r8 = lane & 7;
    const uint32_t a_off = (uint32_t)((wm + ((lane >> 3) & 1) * 8 + r8) * AP + (lane >> 4) * 8) * 2;
    const uint32_t b_off = (uint32_t)((wn + (lane >> 4) * 8 + r8) * AP + ((lane >> 3) & 1) * 8) * 2;

    auto load_tile = [&](int t, int buf) {
        const int k0 = t * BK + lseg * 16;            // halves
        const __half* arow;
        if (mode == 3) {
            arow = g_Oh + ((size_t)(ab * HH + (k0 >> 6)) * NN + an) * DH + (k0 & 63);
        } else {
            arow = A + (size_t)am * DM + k0;
        }
        const __half* brow = brow_base + k0;
        #pragma unroll
        for (int f = 0; f < 2; f++) {
            cp16(sa_u[buf] + dst_off + f * 16, arow + f * 8);
            cp16(sb_u[buf] + dst_off + f * 16, brow + f * 8);
        }
    };

    float acc[4][4][4] = {};

    load_tile(0, 0);
    cp_commit();

    for (int t = 0; t < KTILES; t++) {
        const int p = t & 1;
        if (t + 1 < KTILES) {
            load_tile(t + 1, 1 - p);
            cp_commit();
            cp_wait<1>();
        } else {
            cp_wait<0>();
        }
        __syncthreads();

        #pragma unroll
        for (int kg = 0; kg < 2; kg++) {              // two k16 groups in BK=32
            const uint32_t kb = kg * 32;              // bytes
            uint32_t af[4][4], bf[4][2];
            #pragma unroll
            for (int mt = 0; mt < 4; mt++)
                LDSM_X4(af[mt][0], af[mt][1], af[mt][2], af[mt][3],
                        sa_u[p] + a_off + (uint32_t)mt * (16*AP*2) + kb);
            #pragma unroll
            for (int ntp = 0; ntp < 2; ntp++)
                LDSM_X4(bf[2*ntp][0], bf[2*ntp][1], bf[2*ntp+1][0], bf[2*ntp+1][1],
                        sb_u[p] + b_off + (uint32_t)ntp * (16*AP*2) + kb);
            #pragma unroll
            for (int mt = 0; mt < 4; mt++)
                #pragma unroll
                for (int nt = 0; nt < 4; nt++)
                    mma_f16(acc[mt][nt], af[mt], bf[nt]);
        }
        __syncthreads();
    }

    #pragma unroll
    for (int mt = 0; mt < 4; mt++) {
        #pragma unroll
        for (int half = 0; half < 2; half++) {
            const int m = m0 + wm + mt * 16 + half * 8 + lr;
            const int b = m >> 11, n = m & (NN - 1);
            #pragma unroll
            for (int nt = 0; nt < 4; nt++) {
                const int c = c0 + wn + nt * 8 + 2 * lc;
                const float v0 = acc[mt][nt][half * 2 + 0];
                const float v1 = acc[mt][nt][half * 2 + 1];
                if (emode == 3) {
                    float2 bv = *(const float2*)&bias[c];
                    *(float2*)&out[(size_t)m * DM + c] = make_float2(v0 + bv.x, v1 + bv.y);
                } else {
                    // Q / K / V: heads layout, half2 store
                    const int h = c >> 6, d = c & 63;
                    __half* dst = (emode == 0) ? g_Qh : (emode == 1) ? g_Kh : g_Vh;
                    uint32_t pk = pack_h2(v0, v1);
                    *(uint32_t*)&dst[(((size_t)(b * HH + h)) * NN + n) * DH + d] = pk;
                }
            }
        }
    }
}

// ---------------------------------------------------------------------------
// L2-normalize K rows ([bh][n][d] fp16, warp per row; lane holds half2)
// ---------------------------------------------------------------------------
__global__ __launch_bounds__(256) void norm_k_rows()
{
    const int w    = (blockIdx.x * 256 + threadIdx.x) >> 5;   // 0 .. BH*NN-1
    const int lane = threadIdx.x & 31;
    uint32_t* p = (uint32_t*)(g_Kh + (size_t)w * DH) + lane;
    uint32_t pk = *p;
    float2 v = __half22float2(*(__half2*)&pk);
    float ss = v.x*v.x + v.y*v.y;
    #pragma unroll
    for (int off = 16; off; off >>= 1) ss += __shfl_xor_sync(0xffffffffu, ss, off);
    const float sc = 1.0f / (sqrtf(ss) + EPSF);
    *p = pack_h2(v.x * sc, v.y * sc);
}

// ---------------------------------------------------------------------------
// fp16 tensor-core flash attention, 2 CTAs/SM, ldmatrix fragment loads.
// K and V tiles both [j][d] in smem; V^T B-frags come from ldmatrix.trans.
// Online-max softmax kept in the R14 structure.
// ---------------------------------------------------------------------------
#define KP 72
#define KV_H (64*KP)                       /* halves per K (or V) buffer */
#define AT_SMEM ((4*KV_H + 128*KP)*2)      /* 55296 bytes */

__global__ __launch_bounds__(256, 2) void attn_h()
{
    extern __shared__ __half smh[];
    __half* Ks[2] = { smh,          smh + 2*KV_H };
    __half* Vs[2] = { smh + KV_H,   smh + 3*KV_H };
    __half* Qs    = smh + 4*KV_H;

    const int tid  = threadIdx.x;
    const int wid  = tid >> 5;
    const int lane = tid & 31;
    const int lr   = lane >> 2;              // 0..7
    const int lc   = lane & 3;               // 0..3
    const int qt   = gridDim.x - 1 - blockIdx.x;   // heavy blocks first
    const int bh   = blockIdx.y;
    const int qbase = qt * 128;
    const int T    = 2 * qt + 2;             // 64-key tiles

    const __half* Qp = g_Qh + (size_t)bh * NN * DH;
    const __half* Kp = g_Kh + (size_t)bh * NN * DH;
    const __half* Vp = g_Vh + (size_t)bh * NN * DH;

    const uint32_t ks_u[2] = { smem_u32(Ks[0]), smem_u32(Ks[1]) };
    const uint32_t vs_u[2] = { smem_u32(Vs[0]), smem_u32(Vs[1]) };
    const uint32_t qs_u = smem_u32(Qs);
    const int ldrow = tid & 63, ldseg = tid >> 6;     // row, 32B segment (0..3)

    auto load_kv = [&](int t, int buf) {
        const int kbase = t * 64;
        const __half* ksrc = Kp + (size_t)(kbase + ldrow) * DH + ldseg * 16;
        const __half* vsrc = Vp + (size_t)(kbase + ldrow) * DH + ldseg * 16;
        const uint32_t doff = (uint32_t)ldrow * (KP*2) + (uint32_t)ldseg * 32;
        #pragma unroll
        for (int f = 0; f < 2; f++) {
            cp16(ks_u[buf] + doff + f * 16, ksrc + f * 8);
            cp16(vs_u[buf] + doff + f * 16, vsrc + f * 8);
        }
    };

    load_kv(0, 0);
    cp_commit();

    // ---- stage Q: L2-normalize + scale 1/8, fp16 (thread covers 32 halves) ----
    {
        const int row = tid >> 1, halfq = tid & 1;
        const uint4* src = (const uint4*)(Qp + (size_t)(qbase + row) * DH + halfq * 32);
        uint4 raw[4];
        float2 v[16];
        float ss = 0.f;
        #pragma unroll
        for (int f = 0; f < 4; f++) {
            raw[f] = src[f];
            v[4*f+0] = __half22float2(*(__half2*)&raw[f].x);
            v[4*f+1] = __half22float2(*(__half2*)&raw[f].y);
            v[4*f+2] = __half22float2(*(__half2*)&raw[f].z);
            v[4*f+3] = __half22float2(*(__half2*)&raw[f].w);
        }
        #pragma unroll
        for (int f = 0; f < 16; f++) ss += v[f].x*v[f].x + v[f].y*v[f].y;
        ss += __shfl_xor_sync(0xffffffffu, ss, 1);
        const float sc = 0.125f / (sqrtf(ss) + EPSF);
        uint4* dst = (uint4*)(Qs + row * KP + halfq * 32);
        #pragma unroll
        for (int f = 0; f < 4; f++) {
            uint4 o;
            o.x = pack_h2(v[4*f+0].x * sc, v[4*f+0].y * sc);
            o.y = pack_h2(v[4*f+1].x * sc, v[4*f+1].y * sc);
            o.z = pack_h2(v[4*f+2].x * sc, v[4*f+2].y * sc);
            o.w = pack_h2(v[4*f+3].x * sc, v[4*f+3].y * sc);
            dst[f] = o;
        }
    }

    // ldmatrix lane-address offsets (bytes)
    const int r8 = lane & 7;
    const uint32_t qa_off = (uint32_t)((16*wid + ((lane >> 3) & 1) * 8 + r8) * KP + (lane >> 4) * 8) * 2;
    const uint32_t kb_off = (uint32_t)(((lane >> 4) * 8 + r8) * KP + ((lane >> 3) & 1) * 8) * 2;
    const uint32_t vb_off = (uint32_t)((((lane >> 3) & 1) * 8 + r8) * KP + (lane >> 4) * 8) * 2;

    float m0r = -INFINITY, m1r = -INFINITY, l0 = 0.f, l1 = 0.f;
    float o[8][4] = {};
    const int q0row = qbase + 16 * wid + lr;
    const int q1row = q0row + 8;

    for (int t = 0; t < T; t++) {
        const int p = t & 1;
        __syncthreads();                       // buf 1-p reads done
        if (t + 1 < T) {
            load_kv(t + 1, 1 - p);
            cp_commit();
            cp_wait<1>();
        } else {
            cp_wait<0>();
        }
        __syncthreads();                       // tile t resident; Qs visible (t=0)

        // ---- S = Q K^T (pre-scaled) ----
        float s[8][4] = {};
        #pragma unroll
        for (int kg = 0; kg < 4; kg++) {       // d in 16-chunks
            const uint32_t kb = kg * 32;       // bytes along d
            uint32_t af[4];
            LDSM_X4(af[0], af[1], af[2], af[3], qs_u + qa_off + kb);
            #pragma unroll
            for (int ntp = 0; ntp < 4; ntp++) {
                uint32_t bk[4];
                LDSM_X4(bk[0], bk[1], bk[2], bk[3],
                        ks_u[p] + kb_off + (uint32_t)ntp * (16*KP*2) + kb);
                mma_f16(s[2*ntp],     af, bk);
                mma_f16(s[2*ntp + 1], af, bk + 2);
            }
        }

        // ---- online softmax on C-fragments (R14 structure) ----
        const int kbase = t * 64;
        const bool diag = (t >= T - 2);
        float mx0 = -INFINITY, mx1 = -INFINITY;
        #pragma unroll
        for (int nt = 0; nt < 8; nt++) {
            #pragma unroll
            for (int c = 0; c < 2; c++) {
                if (diag) {
                    const int j = kbase + 8*nt + 2*lc + c;
                    if (j > q0row) s[nt][c]     = -INFINITY;
                    if (j > q1row) s[nt][2 + c] = -INFINITY;
                }
                mx0 = fmaxf(mx0, s[nt][c]);
                mx1 = fmaxf(mx1, s[nt][2 + c]);
            }
        }
        mx0 = fmaxf(mx0, __shfl_xor_sync(0xffffffffu, mx0, 1));
        mx0 = fmaxf(mx0, __shfl_xor_sync(0xffffffffu, mx0, 2));
        mx1 = fmaxf(mx1, __shfl_xor_sync(0xffffffffu, mx1, 1));
        mx1 = fmaxf(mx1, __shfl_xor_sync(0xffffffffu, mx1, 2));
        const float mn0 = fmaxf(m0r, mx0), mn1 = fmaxf(m1r, mx1);
        const float cr0 = __expf(m0r - mn0), cr1 = __expf(m1r - mn1);
        float sum0 = 0.f, sum1 = 0.f;
        #pragma unroll
        for (int nt = 0; nt < 8; nt++) {
            #pragma unroll
            for (int c = 0; c < 2; c++) {
                float p0 = __expf(s[nt][c]     - mn0);
                float p1 = __expf(s[nt][2 + c] - mn1);
                s[nt][c] = p0;  s[nt][2 + c] = p1;
                sum0 += p0; sum1 += p1;
            }
        }
        sum0 += __shfl_xor_sync(0xffffffffu, sum0, 1);
        sum0 += __shfl_xor_sync(0xffffffffu, sum0, 2);
        sum1 += __shfl_xor_sync(0xffffffffu, sum1, 1);
        sum1 += __shfl_xor_sync(0xffffffffu, sum1, 2);
        l0 = l0 * cr0 + sum0;  m0r = mn0;
        l1 = l1 * cr1 + sum1;  m1r = mn1;
        #pragma unroll
        for (int nt = 0; nt < 8; nt++) {
            o[nt][0] *= cr0; o[nt][1] *= cr0;
            o[nt][2] *= cr1; o[nt][3] *= cr1;
        }

        // ---- O += P V  (P via f16x2 packs; V^T frags via ldmatrix.trans) ----
        #pragma unroll
        for (int kg = 0; kg < 4; kg++) {       // j in 16-chunks = jt pair (2kg, 2kg+1)
            uint32_t ap[4];
            ap[0] = pack_h2(s[2*kg  ][0], s[2*kg  ][1]);
            ap[1] = pack_h2(s[2*kg  ][2], s[2*kg  ][3]);
            ap[2] = pack_h2(s[2*kg+1][0], s[2*kg+1][1]);
            ap[3] = pack_h2(s[2*kg+1][2], s[2*kg+1][3]);
            #pragma unroll
            for (int ntp = 0; ntp < 4; ntp++) {
                uint32_t bv[4];
                LDSM_X4_T(bv[0], bv[1], bv[2], bv[3],
                          vs_u[p] + vb_off + (uint32_t)kg * (16*KP*2) + (uint32_t)ntp * 32);
                mma_f16(o[2*ntp],     ap, bv);
                mma_f16(o[2*ntp + 1], ap, bv + 2);
            }
        }
    }

    // ---- epilogue: O /= l, fp16, heads layout ----
    const float inv0 = 1.0f / l0, inv1 = 1.0f / l1;
    __half* Op = g_Oh + (size_t)bh * NN * DH;
    __half* o0 = Op + (size_t)q0row * DH + 2 * lc;
    __half* o1 = Op + (size_t)q1row * DH + 2 * lc;
    #pragma unroll
    for (int nt = 0; nt < 8; nt++) {
        *(uint32_t*)(o0 + 8*nt) = pack_h2(o[nt][0] * inv0, o[nt][1] * inv0);
        *(uint32_t*)(o1 + 8*nt) = pack_h2(o[nt][2] * inv1, o[nt][3] * inv1);
    }
}

// ---------------------------------------------------------------------------
extern "C" void kernel_launch(void* const* d_in, const int* in_sizes, int n_in,
                              void* d_out, int out_size)
{
    const float* X  = (const float*)d_in[0];
    const float* Wq = (const float*)d_in[1];
    const float* Wk = (const float*)d_in[2];
    const float* Wv = (const float*)d_in[3];
    const float* Wo = (const float*)d_in[4];
    const float* bo = (const float*)d_in[5];
    float* out = (float*)d_out;

    cudaFuncSetAttribute(gemm_h, cudaFuncAttributeMaxDynamicSharedMemorySize, GEMM_SMEM);
    cudaFuncSetAttribute(attn_h, cudaFuncAttributeMaxDynamicSharedMemorySize, AT_SMEM);

    round_x<<<(MM*DM)/(4*256), 256>>>(X);
    transpose_w4<<<dim3(32, 32, 4), dim3(32, 8)>>>(Wq, Wk, Wv, Wo);

    // __device__ symbols must be resolved to device addresses host-side.
    __half* wh = nullptr;
    cudaGetSymbolAddress((void**)&wh, g_Wh);
    __half* xh = nullptr;
    cudaGetSymbolAddress((void**)&xh, g_Xh);

    // fused QKV projection: C[4096 x 3072], 768 CTAs
    gemm_h<<<dim3(3*DM/128, MM/128), 256, GEMM_SMEM>>>(xh, wh, nullptr, nullptr, -1);

    norm_k_rows<<<(BH*NN)/8, 256>>>();

    attn_h<<<dim3(NN/128, BH), 256, AT_SMEM>>>();

    gemm_h<<<dim3(DM/128, MM/128), 256, GEMM_SMEM>>>(nullptr, wh + 3*(size_t)DM*DM, bo, out, 3);
}